// round 2
// baseline (speedup 1.0000x reference)
#include <cuda_runtime.h>
#include <cuda_bf16.h>

#define N_NODES 100000
#define N_EDGES 1600000
#define IN_CH 128
#define HID1 64
#define HID2 64
#define HID3 256
#define OUT_CH 64

// ---------------- scratch (device globals; no allocation allowed) ----------------
__device__ float g_deg[N_NODES];
__device__ float g_dinv[N_NODES];
__device__ float g_h1[(size_t)N_NODES * 64];   // gemm outputs (64-wide)
__device__ float g_h2[(size_t)N_NODES * 64];   // activations (64-wide)
__device__ float g_agg[(size_t)N_NODES * 64];  // scatter accumulator
__device__ float g_h3[(size_t)N_NODES * 256];  // 256-wide hidden
__device__ int   g_is64;                       // edge_index dtype flag

// ---------------- index dtype detection ----------------
// If edge_index is int64 little-endian with values < 2^31, every odd 32-bit
// word is zero. If int32 random in [0,100000), odd words ~never all zero.
__global__ void k_detect(const int* ei) {
    if (threadIdx.x == 0 && blockIdx.x == 0) {
        int is64 = 1;
        #pragma unroll 1
        for (int i = 0; i < 64; i++) {
            if (ei[2 * i + 1] != 0) { is64 = 0; break; }
        }
        g_is64 = is64;
    }
}

__device__ __forceinline__ int load_idx(const void* ei, long long i, int is64) {
    if (is64) return (int)__ldg(((const long long*)ei) + i);
    return __ldg(((const int*)ei) + i);
}

// ---------------- degree / dinv ----------------
__global__ void k_deg(const void* __restrict__ ei) {
    int e = blockIdx.x * blockDim.x + threadIdx.x;
    if (e >= N_EDGES) return;
    int d = load_idx(ei, (long long)N_EDGES + e, g_is64);
    atomicAdd(&g_deg[d], 1.0f);
}

__global__ void k_dinv() {
    int i = blockIdx.x * blockDim.x + threadIdx.x;
    if (i >= N_NODES) return;
    g_dinv[i] = rsqrtf(g_deg[i] + 1.0f);
}

// ---------------- edge scatter: agg[dst] += h[src] * dinv[src]*dinv[dst] ----------------
// 64-wide features; each thread handles 4 channels of one edge (float4 gather).
__global__ __launch_bounds__(256) void k_edge(const float* __restrict__ h,
                                              const void* __restrict__ ei,
                                              float* __restrict__ agg) {
    long long t = (long long)blockIdx.x * blockDim.x + threadIdx.x;
    if (t >= (long long)N_EDGES * 16) return;
    int e  = (int)(t >> 4);
    int c4 = ((int)t & 15) << 2;
    int is64 = g_is64;
    int s = load_idx(ei, e, is64);
    int d = load_idx(ei, (long long)N_EDGES + e, is64);
    float norm = g_dinv[s] * g_dinv[d];
    float4 v = *(const float4*)(h + ((long long)s << 6) + c4);
    float* o = agg + ((long long)d << 6) + c4;
    atomicAdd(o + 0, v.x * norm);
    atomicAdd(o + 1, v.y * norm);
    atomicAdd(o + 2, v.z * norm);
    atomicAdd(o + 3, v.w * norm);
}

// ---------------- post: out = relu(agg + h*dinv^2 + b) (64-wide) ----------------
__global__ __launch_bounds__(256) void k_post(const float* __restrict__ hlin,
                                              const float* __restrict__ agg,
                                              const float* __restrict__ bias,
                                              float* __restrict__ out) {
    long long t = (long long)blockIdx.x * blockDim.x + threadIdx.x;
    if (t >= (long long)N_NODES * 64) return;
    int i = (int)(t >> 6);
    int c = (int)(t & 63);
    float di = g_dinv[i];
    float v = agg[t] + hlin[t] * (di * di) + bias[c];
    out[t] = fmaxf(v, 0.0f);
}

// ---------------- SGEMM: C[N,NOUT] = A[N,K] @ W[K,NOUT] (+bias) (+relu) ----------------
// BM=64, BN=64, BK=16, 256 threads, 4x4 microtile per thread.
// Requires: K % 16 == 0, NOUT % 64 == 0. Row guard on N.
__global__ __launch_bounds__(256) void k_gemm(const float* __restrict__ A,
                                              const float* __restrict__ W,
                                              const float* __restrict__ bias,
                                              float* __restrict__ C,
                                              int N, int K, int NOUT, int relu) {
    __shared__ float As[16][64];
    __shared__ float Bs[16][64];

    int r0 = blockIdx.x * 64;
    int c0 = blockIdx.y * 64;
    int tid = threadIdx.x;
    int tx = tid & 15;       // col group
    int ty = tid >> 4;       // row group

    int arow = tid >> 2;           // 0..63
    int ak4  = (tid & 3) << 2;     // 0,4,8,12
    int wrow = tid >> 4;           // 0..15
    int wc4  = (tid & 15) << 2;    // 0..60

    float acc[4][4];
    #pragma unroll
    for (int i = 0; i < 4; i++)
        #pragma unroll
        for (int j = 0; j < 4; j++) acc[i][j] = 0.0f;

    for (int kk = 0; kk < K; kk += 16) {
        // load A tile (transposed into smem)
        float4 av = make_float4(0.f, 0.f, 0.f, 0.f);
        int gr = r0 + arow;
        if (gr < N) av = *(const float4*)&A[(long long)gr * K + kk + ak4];
        As[ak4 + 0][arow] = av.x;
        As[ak4 + 1][arow] = av.y;
        As[ak4 + 2][arow] = av.z;
        As[ak4 + 3][arow] = av.w;
        // load W tile
        float4 wv = *(const float4*)&W[(long long)(kk + wrow) * NOUT + c0 + wc4];
        *(float4*)&Bs[wrow][wc4] = wv;
        __syncthreads();

        #pragma unroll
        for (int k = 0; k < 16; k++) {
            float a0 = As[k][ty * 4 + 0];
            float a1 = As[k][ty * 4 + 1];
            float a2 = As[k][ty * 4 + 2];
            float a3 = As[k][ty * 4 + 3];
            float4 b = *(const float4*)&Bs[k][tx * 4];
            acc[0][0] += a0 * b.x; acc[0][1] += a0 * b.y; acc[0][2] += a0 * b.z; acc[0][3] += a0 * b.w;
            acc[1][0] += a1 * b.x; acc[1][1] += a1 * b.y; acc[1][2] += a1 * b.z; acc[1][3] += a1 * b.w;
            acc[2][0] += a2 * b.x; acc[2][1] += a2 * b.y; acc[2][2] += a2 * b.z; acc[2][3] += a2 * b.w;
            acc[3][0] += a3 * b.x; acc[3][1] += a3 * b.y; acc[3][2] += a3 * b.z; acc[3][3] += a3 * b.w;
        }
        __syncthreads();
    }

    float bv[4] = {0.f, 0.f, 0.f, 0.f};
    if (bias) {
        #pragma unroll
        for (int j = 0; j < 4; j++) bv[j] = bias[c0 + tx * 4 + j];
    }
    #pragma unroll
    for (int i = 0; i < 4; i++) {
        int gr = r0 + ty * 4 + i;
        if (gr < N) {
            float4 o;
            float v0 = acc[i][0] + bv[0];
            float v1 = acc[i][1] + bv[1];
            float v2 = acc[i][2] + bv[2];
            float v3 = acc[i][3] + bv[3];
            if (relu) { v0 = fmaxf(v0, 0.f); v1 = fmaxf(v1, 0.f); v2 = fmaxf(v2, 0.f); v3 = fmaxf(v3, 0.f); }
            o.x = v0; o.y = v1; o.z = v2; o.w = v3;
            *(float4*)&C[(long long)gr * NOUT + c0 + tx * 4] = o;
        }
    }
}

// ---------------- log_softmax over 64 cols, one warp per row, in place ----------------
__global__ __launch_bounds__(256) void k_lsm(float* __restrict__ out, int N) {
    int warp = (blockIdx.x * blockDim.x + threadIdx.x) >> 5;
    int lane = threadIdx.x & 31;
    if (warp >= N) return;
    float* row = out + (long long)warp * 64;
    float v0 = row[lane];
    float v1 = row[lane + 32];
    float m = fmaxf(v0, v1);
    #pragma unroll
    for (int o = 16; o; o >>= 1) m = fmaxf(m, __shfl_xor_sync(0xffffffffu, m, o));
    float s = expf(v0 - m) + expf(v1 - m);
    #pragma unroll
    for (int o = 16; o; o >>= 1) s += __shfl_xor_sync(0xffffffffu, s, o);
    float lse = m + logf(s);
    row[lane] = v0 - lse;
    row[lane + 32] = v1 - lse;
}

// ---------------- launch ----------------
extern "C" void kernel_launch(void* const* d_in, const int* in_sizes, int n_in,
                              void* d_out, int out_size) {
    const float* x  = (const float*)d_in[0];
    const void*  ei = d_in[1];
    const float* W1 = (const float*)d_in[2];
    const float* b1 = (const float*)d_in[3];
    const float* W2 = (const float*)d_in[4];
    const float* b2 = (const float*)d_in[5];
    const float* W3 = (const float*)d_in[6];
    const float* b3 = (const float*)d_in[7];
    const float* W4 = (const float*)d_in[8];
    const float* b4 = (const float*)d_in[9];
    float* out = (float*)d_out;

    void *p_deg, *p_h1, *p_h2, *p_agg, *p_h3;
    cudaGetSymbolAddress(&p_deg, g_deg);
    cudaGetSymbolAddress(&p_h1, g_h1);
    cudaGetSymbolAddress(&p_h2, g_h2);
    cudaGetSymbolAddress(&p_agg, g_agg);
    cudaGetSymbolAddress(&p_h3, g_h3);
    float* h1  = (float*)p_h1;
    float* h2  = (float*)p_h2;
    float* agg = (float*)p_agg;
    float* h3  = (float*)p_h3;

    const int TB = 256;
    dim3 gemm_grid1((N_NODES + 63) / 64, 1);
    dim3 gemm_grid4((N_NODES + 63) / 64, 4);
    int edge_blocks = (int)(((long long)N_EDGES * 16 + TB - 1) / TB);
    int post_blocks = (int)(((long long)N_NODES * 64 + TB - 1) / TB);

    // degree + dinv
    k_detect<<<1, 32>>>((const int*)ei);
    cudaMemsetAsync(p_deg, 0, (size_t)N_NODES * sizeof(float));
    k_deg<<<(N_EDGES + TB - 1) / TB, TB>>>(ei);
    k_dinv<<<(N_NODES + TB - 1) / TB, TB>>>();

    // layer 1: gemm(x,W1) -> h1 ; aggregate ; post(relu) -> h2
    k_gemm<<<gemm_grid1, TB>>>(x, W1, nullptr, h1, N_NODES, IN_CH, HID1, 0);
    cudaMemsetAsync(p_agg, 0, (size_t)N_NODES * 64 * sizeof(float));
    k_edge<<<edge_blocks, TB>>>(h1, ei, agg);
    k_post<<<post_blocks, TB>>>(h1, agg, b1, h2);

    // layer 2: gemm(h2,W2) -> h1 ; aggregate ; post(relu) -> h2
    k_gemm<<<gemm_grid1, TB>>>(h2, W2, nullptr, h1, N_NODES, HID1, HID2, 0);
    cudaMemsetAsync(p_agg, 0, (size_t)N_NODES * 64 * sizeof(float));
    k_edge<<<edge_blocks, TB>>>(h1, ei, agg);
    k_post<<<post_blocks, TB>>>(h1, agg, b2, h2);

    // layer 3: h3 = h2 @ W3 + b3
    k_gemm<<<gemm_grid4, TB>>>(h2, W3, b3, h3, N_NODES, HID2, HID3, 0);

    // layer 4: out = h3 @ W4 + b4 ; log_softmax in place
    k_gemm<<<gemm_grid1, TB>>>(h3, W4, b4, out, N_NODES, HID3, OUT_CH, 0);
    k_lsm<<<((long long)N_NODES * 32 + TB - 1) / TB, TB>>>(out, N_NODES);
}

// round 3
// speedup vs baseline: 1.6071x; 1.6071x over previous
#include <cuda_runtime.h>
#include <cuda_bf16.h>

#define N_NODES 100000
#define N_EDGES 1600000
#define IN_CH 128
#define HID1 64
#define HID2 64
#define HID3 256
#define OUT_CH 64

// ---------------- scratch (device globals; no allocation allowed) ----------------
__device__ float g_deg[N_NODES];
__device__ float g_dinv[N_NODES];
__device__ int   g_rs[N_NODES];                // CSR row start
__device__ int   g_cur[N_NODES];               // scatter cursors
__device__ int2  g_csr[N_EDGES];               // {src, norm-as-bits} sorted by dst
__device__ float g_h1[(size_t)N_NODES * 64];   // gemm outputs (64-wide)
__device__ float g_h2[(size_t)N_NODES * 64];   // activations (64-wide)
__device__ float g_h3[(size_t)N_NODES * 256];  // 256-wide hidden
__device__ int   g_is64;                       // edge_index dtype flag

// ---------------- index dtype detection ----------------
// If edge_index is int64 little-endian with values < 2^31, every odd 32-bit
// word is zero. If int32 random in [0,100000), odd words ~never all zero.
__global__ void k_detect(const int* ei) {
    if (threadIdx.x == 0 && blockIdx.x == 0) {
        int is64 = 1;
        #pragma unroll 1
        for (int i = 0; i < 64; i++) {
            if (ei[2 * i + 1] != 0) { is64 = 0; break; }
        }
        g_is64 = is64;
    }
}

__device__ __forceinline__ int load_idx(const void* ei, long long i, int is64) {
    if (is64) return (int)__ldg(((const long long*)ei) + i);
    return __ldg(((const int*)ei) + i);
}

// ---------------- degree ----------------
__global__ void k_deg(const void* __restrict__ ei) {
    int e = blockIdx.x * blockDim.x + threadIdx.x;
    if (e >= N_EDGES) return;
    int d = load_idx(ei, (long long)N_EDGES + e, g_is64);
    atomicAdd(&g_deg[d], 1.0f);
}

__global__ void k_dinv() {
    int i = blockIdx.x * blockDim.x + threadIdx.x;
    if (i >= N_NODES) return;
    g_dinv[i] = rsqrtf(g_deg[i] + 1.0f);
}

// ---------------- exclusive scan of degrees -> row starts + cursors ----------------
// Single block, 1024 threads, 4 items/thread per 4096-chunk, Hillis-Steele on chunk sums.
__global__ __launch_bounds__(1024) void k_scan() {
    __shared__ int s[1024];
    __shared__ int run_s;
    int t = threadIdx.x;
    if (t == 0) run_s = 0;
    __syncthreads();
    for (int base = 0; base < N_NODES; base += 4096) {
        int idx = base + t * 4;
        int c0 = 0, c1 = 0, c2 = 0, c3 = 0;
        if (idx + 0 < N_NODES) c0 = (int)g_deg[idx + 0];
        if (idx + 1 < N_NODES) c1 = (int)g_deg[idx + 1];
        if (idx + 2 < N_NODES) c2 = (int)g_deg[idx + 2];
        if (idx + 3 < N_NODES) c3 = (int)g_deg[idx + 3];
        int tsum = c0 + c1 + c2 + c3;
        s[t] = tsum;
        __syncthreads();
        #pragma unroll 1
        for (int off = 1; off < 1024; off <<= 1) {
            int x = (t >= off) ? s[t - off] : 0;
            __syncthreads();
            s[t] += x;
            __syncthreads();
        }
        int p = run_s + s[t] - tsum;
        if (idx + 0 < N_NODES) { g_rs[idx + 0] = p; g_cur[idx + 0] = p; p += c0; }
        if (idx + 1 < N_NODES) { g_rs[idx + 1] = p; g_cur[idx + 1] = p; p += c1; }
        if (idx + 2 < N_NODES) { g_rs[idx + 2] = p; g_cur[idx + 2] = p; p += c2; }
        if (idx + 3 < N_NODES) { g_rs[idx + 3] = p; g_cur[idx + 3] = p; p += c3; }
        __syncthreads();
        if (t == 0) run_s += s[1023];
        __syncthreads();
    }
}

// ---------------- fill CSR: g_csr[pos] = {src, dinv[src]*dinv[dst]} ----------------
__global__ void k_fill(const void* __restrict__ ei) {
    int e = blockIdx.x * blockDim.x + threadIdx.x;
    if (e >= N_EDGES) return;
    int is64 = g_is64;
    int s = load_idx(ei, e, is64);
    int d = load_idx(ei, (long long)N_EDGES + e, is64);
    float norm = g_dinv[s] * g_dinv[d];
    int pos = atomicAdd(&g_cur[d], 1);
    g_csr[pos] = make_int2(s, __float_as_int(norm));
}

// ---------------- fused aggregate + self-loop + bias + relu (64-wide) ----------------
// One warp per dst node: gather h[src]*norm over CSR range, no atomics.
__global__ __launch_bounds__(256) void k_agg(const float* __restrict__ h,
                                             const float* __restrict__ bias,
                                             float* __restrict__ out) {
    int warp = (int)((blockIdx.x * 256 + threadIdx.x) >> 5);
    int lane = threadIdx.x & 31;
    if (warp >= N_NODES) return;
    int i = warp;
    int start = g_rs[i];
    int end = start + (int)g_deg[i];
    float di = g_dinv[i];
    float sl = di * di;
    const float* hrow = h + ((size_t)i << 6);
    float acc0 = hrow[lane] * sl;
    float acc1 = hrow[lane + 32] * sl;
    int e = start;
    for (; e + 3 < end; e += 4) {
        int2 r0 = __ldg(&g_csr[e + 0]);
        int2 r1 = __ldg(&g_csr[e + 1]);
        int2 r2 = __ldg(&g_csr[e + 2]);
        int2 r3 = __ldg(&g_csr[e + 3]);
        const float* p0 = h + ((size_t)r0.x << 6);
        const float* p1 = h + ((size_t)r1.x << 6);
        const float* p2 = h + ((size_t)r2.x << 6);
        const float* p3 = h + ((size_t)r3.x << 6);
        float n0 = __int_as_float(r0.y), n1 = __int_as_float(r1.y);
        float n2 = __int_as_float(r2.y), n3 = __int_as_float(r3.y);
        float a00 = p0[lane], a01 = p0[lane + 32];
        float a10 = p1[lane], a11 = p1[lane + 32];
        float a20 = p2[lane], a21 = p2[lane + 32];
        float a30 = p3[lane], a31 = p3[lane + 32];
        acc0 += a00 * n0; acc1 += a01 * n0;
        acc0 += a10 * n1; acc1 += a11 * n1;
        acc0 += a20 * n2; acc1 += a21 * n2;
        acc0 += a30 * n3; acc1 += a31 * n3;
    }
    for (; e < end; e++) {
        int2 r = __ldg(&g_csr[e]);
        float n = __int_as_float(r.y);
        const float* p = h + ((size_t)r.x << 6);
        acc0 += p[lane] * n;
        acc1 += p[lane + 32] * n;
    }
    float v0 = acc0 + bias[lane];
    float v1 = acc1 + bias[lane + 32];
    out[((size_t)i << 6) + lane]      = fmaxf(v0, 0.0f);
    out[((size_t)i << 6) + lane + 32] = fmaxf(v1, 0.0f);
}

// ---------------- SGEMM: C[N,NOUT] = A[N,K] @ W[K,NOUT] (+bias) ----------------
// BM=128, BN=64, BK=16, 256 threads, 8x4 microtile per thread.
// Requires: K % 16 == 0, NOUT % 64 == 0. Row guard on N.
__global__ __launch_bounds__(256) void k_gemm(const float* __restrict__ A,
                                              const float* __restrict__ W,
                                              const float* __restrict__ bias,
                                              float* __restrict__ C,
                                              int N, int K, int NOUT, int relu) {
    __shared__ float As[16][128];
    __shared__ float Bs[16][64];

    int r0 = blockIdx.x * 128;
    int c0 = blockIdx.y * 64;
    int tid = threadIdx.x;
    int tx = tid & 15;        // col group (4 cols)
    int ty = tid >> 4;        // row group (8 rows)

    int arow = tid >> 1;          // 0..127
    int ak8  = (tid & 1) << 3;    // 0 or 8
    int wrow = tid >> 4;          // 0..15
    int wc4  = (tid & 15) << 2;   // 0..60

    float acc[8][4];
    #pragma unroll
    for (int i = 0; i < 8; i++)
        #pragma unroll
        for (int j = 0; j < 4; j++) acc[i][j] = 0.0f;

    for (int kk = 0; kk < K; kk += 16) {
        float4 a0 = make_float4(0.f, 0.f, 0.f, 0.f);
        float4 a1 = make_float4(0.f, 0.f, 0.f, 0.f);
        int gr = r0 + arow;
        if (gr < N) {
            const float* ap = A + (size_t)gr * K + kk + ak8;
            a0 = *(const float4*)ap;
            a1 = *(const float4*)(ap + 4);
        }
        As[ak8 + 0][arow] = a0.x;
        As[ak8 + 1][arow] = a0.y;
        As[ak8 + 2][arow] = a0.z;
        As[ak8 + 3][arow] = a0.w;
        As[ak8 + 4][arow] = a1.x;
        As[ak8 + 5][arow] = a1.y;
        As[ak8 + 6][arow] = a1.z;
        As[ak8 + 7][arow] = a1.w;
        *(float4*)&Bs[wrow][wc4] = *(const float4*)&W[(size_t)(kk + wrow) * NOUT + c0 + wc4];
        __syncthreads();

        #pragma unroll
        for (int k = 0; k < 16; k++) {
            float4 b = *(const float4*)&Bs[k][tx * 4];
            float ar[8];
            #pragma unroll
            for (int i = 0; i < 8; i++) ar[i] = As[k][ty * 8 + i];
            #pragma unroll
            for (int i = 0; i < 8; i++) {
                acc[i][0] += ar[i] * b.x;
                acc[i][1] += ar[i] * b.y;
                acc[i][2] += ar[i] * b.z;
                acc[i][3] += ar[i] * b.w;
            }
        }
        __syncthreads();
    }

    float4 bv = make_float4(0.f, 0.f, 0.f, 0.f);
    if (bias) bv = *(const float4*)&bias[c0 + tx * 4];
    #pragma unroll
    for (int i = 0; i < 8; i++) {
        int gr = r0 + ty * 8 + i;
        if (gr < N) {
            float v0 = acc[i][0] + bv.x;
            float v1 = acc[i][1] + bv.y;
            float v2 = acc[i][2] + bv.z;
            float v3 = acc[i][3] + bv.w;
            if (relu) {
                v0 = fmaxf(v0, 0.f); v1 = fmaxf(v1, 0.f);
                v2 = fmaxf(v2, 0.f); v3 = fmaxf(v3, 0.f);
            }
            float4 o = make_float4(v0, v1, v2, v3);
            *(float4*)&C[(size_t)gr * NOUT + c0 + tx * 4] = o;
        }
    }
}

// ---------------- log_softmax over 64 cols, one warp per row, in place ----------------
__global__ __launch_bounds__(256) void k_lsm(float* __restrict__ out, int N) {
    int warp = (blockIdx.x * blockDim.x + threadIdx.x) >> 5;
    int lane = threadIdx.x & 31;
    if (warp >= N) return;
    float* row = out + (long long)warp * 64;
    float v0 = row[lane];
    float v1 = row[lane + 32];
    float m = fmaxf(v0, v1);
    #pragma unroll
    for (int o = 16; o; o >>= 1) m = fmaxf(m, __shfl_xor_sync(0xffffffffu, m, o));
    float s = expf(v0 - m) + expf(v1 - m);
    #pragma unroll
    for (int o = 16; o; o >>= 1) s += __shfl_xor_sync(0xffffffffu, s, o);
    float lse = m + logf(s);
    row[lane] = v0 - lse;
    row[lane + 32] = v1 - lse;
}

// ---------------- launch ----------------
extern "C" void kernel_launch(void* const* d_in, const int* in_sizes, int n_in,
                              void* d_out, int out_size) {
    const float* x  = (const float*)d_in[0];
    const void*  ei = d_in[1];
    const float* W1 = (const float*)d_in[2];
    const float* b1 = (const float*)d_in[3];
    const float* W2 = (const float*)d_in[4];
    const float* b2 = (const float*)d_in[5];
    const float* W3 = (const float*)d_in[6];
    const float* b3 = (const float*)d_in[7];
    const float* W4 = (const float*)d_in[8];
    const float* b4 = (const float*)d_in[9];
    float* out = (float*)d_out;

    void *p_deg, *p_h1, *p_h2, *p_h3;
    cudaGetSymbolAddress(&p_deg, g_deg);
    cudaGetSymbolAddress(&p_h1, g_h1);
    cudaGetSymbolAddress(&p_h2, g_h2);
    cudaGetSymbolAddress(&p_h3, g_h3);
    float* h1 = (float*)p_h1;
    float* h2 = (float*)p_h2;
    float* h3 = (float*)p_h3;

    const int TB = 256;
    dim3 gg1((N_NODES + 127) / 128, 1);
    dim3 gg4((N_NODES + 127) / 128, 4);
    int agg_blocks = (N_NODES * 32 + TB - 1) / TB;   // warp per node

    // graph preprocessing: degree, dinv, CSR
    k_detect<<<1, 32>>>((const int*)ei);
    cudaMemsetAsync(p_deg, 0, (size_t)N_NODES * sizeof(float));
    k_deg<<<(N_EDGES + TB - 1) / TB, TB>>>(ei);
    k_dinv<<<(N_NODES + TB - 1) / TB, TB>>>();
    k_scan<<<1, 1024>>>();
    k_fill<<<(N_EDGES + TB - 1) / TB, TB>>>(ei);

    // layer 1: gemm(x,W1) -> h1 ; fused aggregate+bias+relu -> h2
    k_gemm<<<gg1, TB>>>(x, W1, nullptr, h1, N_NODES, IN_CH, HID1, 0);
    k_agg<<<agg_blocks, TB>>>(h1, b1, h2);

    // layer 2: gemm(h2,W2) -> h1 ; fused aggregate+bias+relu -> h2
    k_gemm<<<gg1, TB>>>(h2, W2, nullptr, h1, N_NODES, HID1, HID2, 0);
    k_agg<<<agg_blocks, TB>>>(h1, b2, h2);

    // layer 3: h3 = h2 @ W3 + b3
    k_gemm<<<gg4, TB>>>(h2, W3, b3, h3, N_NODES, HID2, HID3, 0);

    // layer 4: out = h3 @ W4 + b4 ; log_softmax in place
    k_gemm<<<gg1, TB>>>(h3, W4, b4, out, N_NODES, HID3, OUT_CH, 0);
    k_lsm<<<(N_NODES * 32 + TB - 1) / TB, TB>>>(out, N_NODES);
}

// round 5
// speedup vs baseline: 2.0658x; 1.2854x over previous
#include <cuda_runtime.h>
#include <cuda_bf16.h>

#define N_NODES 100000
#define N_EDGES 1600000
#define IN_CH 128
#define HID1 64
#define HID2 64
#define HID3 256
#define OUT_CH 64
#define SCAN_NB ((N_NODES + 1023) / 1024)   // 98

// ---------------- scratch (device globals; no allocation allowed) ----------------
__device__ float g_deg[N_NODES];
__device__ float g_dinv[N_NODES];
__device__ int   g_rs[N_NODES];                // CSR row start (exclusive scan)
__device__ int   g_cur[N_NODES];               // scatter cursors
__device__ int   g_bsum[128];                  // per-block scan sums
__device__ int   g_boff[128];                  // per-block offsets
__device__ int2  g_csr[N_EDGES];               // {src, norm-as-bits} grouped by dst
__device__ float g_h1[(size_t)N_NODES * 64];
__device__ float g_h2[(size_t)N_NODES * 64];
__device__ float g_h3[(size_t)N_NODES * 256];
__device__ int   g_is64;

// ---------------- index dtype detection ----------------
__global__ void k_detect(const int* ei) {
    if (threadIdx.x == 0 && blockIdx.x == 0) {
        int is64 = 1;
        #pragma unroll 1
        for (int i = 0; i < 64; i++) {
            if (ei[2 * i + 1] != 0) { is64 = 0; break; }
        }
        g_is64 = is64;
    }
}

__device__ __forceinline__ int load_idx(const void* ei, long long i, int is64) {
    if (is64) return (int)__ldg(((const long long*)ei) + i);
    return __ldg(((const int*)ei) + i);
}

// ---------------- degree ----------------
__global__ void k_deg(const void* __restrict__ ei) {
    int e = blockIdx.x * blockDim.x + threadIdx.x;
    if (e >= N_EDGES) return;
    int d = load_idx(ei, (long long)N_EDGES + e, g_is64);
    atomicAdd(&g_deg[d], 1.0f);
}

__global__ void k_dinv() {
    int i = blockIdx.x * blockDim.x + threadIdx.x;
    if (i >= N_NODES) return;
    g_dinv[i] = rsqrtf(g_deg[i] + 1.0f);
}

// ---------------- 3-phase multi-block exclusive scan ----------------
__global__ __launch_bounds__(1024) void k_scan1() {
    __shared__ int s[1024];
    int t = threadIdx.x;
    int i = blockIdx.x * 1024 + t;
    int v = (i < N_NODES) ? (int)g_deg[i] : 0;
    s[t] = v;
    __syncthreads();
    #pragma unroll 1
    for (int off = 1; off < 1024; off <<= 1) {
        int x = (t >= off) ? s[t - off] : 0;
        __syncthreads();
        s[t] += x;
        __syncthreads();
    }
    if (i < N_NODES) g_rs[i] = s[t] - v;   // exclusive within block
    if (t == 1023) g_bsum[blockIdx.x] = s[1023];
}

__global__ __launch_bounds__(128) void k_scan2() {
    __shared__ int s[128];
    int t = threadIdx.x;
    int v = (t < SCAN_NB) ? g_bsum[t] : 0;
    s[t] = v;
    __syncthreads();
    #pragma unroll 1
    for (int off = 1; off < 128; off <<= 1) {
        int x = (t >= off) ? s[t - off] : 0;
        __syncthreads();
        s[t] += x;
        __syncthreads();
    }
    if (t < SCAN_NB) g_boff[t] = s[t] - v;
}

__global__ __launch_bounds__(1024) void k_scan3() {
    int i = blockIdx.x * 1024 + threadIdx.x;
    if (i >= N_NODES) return;
    int r = g_rs[i] + g_boff[blockIdx.x];
    g_rs[i] = r;
    g_cur[i] = r;
}

// ---------------- fill CSR ----------------
__global__ void k_fill(const void* __restrict__ ei) {
    int e = blockIdx.x * blockDim.x + threadIdx.x;
    if (e >= N_EDGES) return;
    int is64 = g_is64;
    int s = load_idx(ei, e, is64);
    int d = load_idx(ei, (long long)N_EDGES + e, is64);
    float norm = g_dinv[s] * g_dinv[d];
    int pos = atomicAdd(&g_cur[d], 1);
    g_csr[pos] = make_int2(s, __float_as_int(norm));
}

// ---------------- fused aggregate + self-loop + bias + relu (64-wide) ----------------
__global__ __launch_bounds__(256) void k_agg(const float* __restrict__ h,
                                             const float* __restrict__ bias,
                                             float* __restrict__ out) {
    int warp = (int)((blockIdx.x * 256 + threadIdx.x) >> 5);
    int lane = threadIdx.x & 31;
    if (warp >= N_NODES) return;
    int i = warp;
    int start = g_rs[i];
    int end = start + (int)g_deg[i];
    float di = g_dinv[i];
    float sl = di * di;
    const float* hrow = h + ((size_t)i << 6);
    float acc0 = hrow[lane] * sl;
    float acc1 = hrow[lane + 32] * sl;
    int e = start;
    for (; e + 3 < end; e += 4) {
        int2 r0 = __ldg(&g_csr[e + 0]);
        int2 r1 = __ldg(&g_csr[e + 1]);
        int2 r2 = __ldg(&g_csr[e + 2]);
        int2 r3 = __ldg(&g_csr[e + 3]);
        const float* p0 = h + ((size_t)r0.x << 6);
        const float* p1 = h + ((size_t)r1.x << 6);
        const float* p2 = h + ((size_t)r2.x << 6);
        const float* p3 = h + ((size_t)r3.x << 6);
        float n0 = __int_as_float(r0.y), n1 = __int_as_float(r1.y);
        float n2 = __int_as_float(r2.y), n3 = __int_as_float(r3.y);
        float a00 = p0[lane], a01 = p0[lane + 32];
        float a10 = p1[lane], a11 = p1[lane + 32];
        float a20 = p2[lane], a21 = p2[lane + 32];
        float a30 = p3[lane], a31 = p3[lane + 32];
        acc0 += a00 * n0; acc1 += a01 * n0;
        acc0 += a10 * n1; acc1 += a11 * n1;
        acc0 += a20 * n2; acc1 += a21 * n2;
        acc0 += a30 * n3; acc1 += a31 * n3;
    }
    for (; e < end; e++) {
        int2 r = __ldg(&g_csr[e]);
        float n = __int_as_float(r.y);
        const float* p = h + ((size_t)r.x << 6);
        acc0 += p[lane] * n;
        acc1 += p[lane + 32] * n;
    }
    float v0 = acc0 + bias[lane];
    float v1 = acc1 + bias[lane + 32];
    out[((size_t)i << 6) + lane]      = fmaxf(v0, 0.0f);
    out[((size_t)i << 6) + lane + 32] = fmaxf(v1, 0.0f);
}

// ---------------- SGEMM: C[N,NOUT] = A[N,K] @ W[K,NOUT] (+bias) (+relu|lsm) ----------------
// BM=128, BN=64, BK=16, 256 threads, 8x4 microtile, double-buffered smem.
// lsm=1 requires NOUT==64 and gridDim.y==1 (full row in one block).
__global__ __launch_bounds__(256) void k_gemm(const float* __restrict__ A,
                                              const float* __restrict__ W,
                                              const float* __restrict__ bias,
                                              float* __restrict__ C,
                                              int N, int K, int NOUT,
                                              int relu, int lsm) {
    __shared__ float As[2][16][128];
    __shared__ float Bs[2][16][64];

    int r0 = blockIdx.x * 128;
    int c0 = blockIdx.y * 64;
    int tid = threadIdx.x;
    int tx = tid & 15;
    int ty = tid >> 4;

    int arow = tid >> 1;
    int ak8  = (tid & 1) << 3;
    int wrow = tid >> 4;
    int wc4  = (tid & 15) << 2;

    float acc[8][4];
    #pragma unroll
    for (int i = 0; i < 8; i++)
        #pragma unroll
        for (int j = 0; j < 4; j++) acc[i][j] = 0.0f;

    int nsteps = K >> 4;
    int gr_a = r0 + arow;

    // preload tile 0
    {
        float4 a0 = make_float4(0.f, 0.f, 0.f, 0.f);
        float4 a1 = make_float4(0.f, 0.f, 0.f, 0.f);
        if (gr_a < N) {
            const float* ap = A + (size_t)gr_a * K + ak8;
            a0 = *(const float4*)ap;
            a1 = *(const float4*)(ap + 4);
        }
        As[0][ak8 + 0][arow] = a0.x; As[0][ak8 + 1][arow] = a0.y;
        As[0][ak8 + 2][arow] = a0.z; As[0][ak8 + 3][arow] = a0.w;
        As[0][ak8 + 4][arow] = a1.x; As[0][ak8 + 5][arow] = a1.y;
        As[0][ak8 + 6][arow] = a1.z; As[0][ak8 + 7][arow] = a1.w;
        *(float4*)&Bs[0][wrow][wc4] = *(const float4*)&W[(size_t)wrow * NOUT + c0 + wc4];
    }
    __syncthreads();

    for (int t = 0; t < nsteps; t++) {
        int cur = t & 1;
        float4 a0, a1, wv;
        bool have_next = (t + 1 < nsteps);
        if (have_next) {
            int kk = (t + 1) << 4;
            a0 = make_float4(0.f, 0.f, 0.f, 0.f);
            a1 = make_float4(0.f, 0.f, 0.f, 0.f);
            if (gr_a < N) {
                const float* ap = A + (size_t)gr_a * K + kk + ak8;
                a0 = *(const float4*)ap;
                a1 = *(const float4*)(ap + 4);
            }
            wv = *(const float4*)&W[(size_t)(kk + wrow) * NOUT + c0 + wc4];
        }

        #pragma unroll
        for (int k = 0; k < 16; k++) {
            float4 b = *(const float4*)&Bs[cur][k][tx * 4];
            float ar[8];
            #pragma unroll
            for (int i = 0; i < 8; i++) ar[i] = As[cur][k][ty * 8 + i];
            #pragma unroll
            for (int i = 0; i < 8; i++) {
                acc[i][0] += ar[i] * b.x;
                acc[i][1] += ar[i] * b.y;
                acc[i][2] += ar[i] * b.z;
                acc[i][3] += ar[i] * b.w;
            }
        }

        if (have_next) {
            int nxt = cur ^ 1;
            As[nxt][ak8 + 0][arow] = a0.x; As[nxt][ak8 + 1][arow] = a0.y;
            As[nxt][ak8 + 2][arow] = a0.z; As[nxt][ak8 + 3][arow] = a0.w;
            As[nxt][ak8 + 4][arow] = a1.x; As[nxt][ak8 + 5][arow] = a1.y;
            As[nxt][ak8 + 6][arow] = a1.z; As[nxt][ak8 + 7][arow] = a1.w;
            *(float4*)&Bs[nxt][wrow][wc4] = wv;
            __syncthreads();
        }
    }

    float4 bv = make_float4(0.f, 0.f, 0.f, 0.f);
    if (bias) bv = *(const float4*)&bias[c0 + tx * 4];

    if (!lsm) {
        #pragma unroll
        for (int i = 0; i < 8; i++) {
            int gr = r0 + ty * 8 + i;
            if (gr < N) {
                float v0 = acc[i][0] + bv.x;
                float v1 = acc[i][1] + bv.y;
                float v2 = acc[i][2] + bv.z;
                float v3 = acc[i][3] + bv.w;
                if (relu) {
                    v0 = fmaxf(v0, 0.f); v1 = fmaxf(v1, 0.f);
                    v2 = fmaxf(v2, 0.f); v3 = fmaxf(v3, 0.f);
                }
                *(float4*)&C[(size_t)gr * NOUT + c0 + tx * 4] = make_float4(v0, v1, v2, v3);
            }
        }
    } else {
        // fused log_softmax over the 64 cols of each row; row is spread over 16
        // lanes (tx) in the same half-warp. xor-shuffles 8/4/2/1 reduce per-row.
        #pragma unroll
        for (int i = 0; i < 8; i++) {
            float v0 = acc[i][0] + bv.x;
            float v1 = acc[i][1] + bv.y;
            float v2 = acc[i][2] + bv.z;
            float v3 = acc[i][3] + bv.w;
            float m = fmaxf(fmaxf(v0, v1), fmaxf(v2, v3));
            #pragma unroll
            for (int o = 8; o; o >>= 1) m = fmaxf(m, __shfl_xor_sync(0xffffffffu, m, o));
            float s = expf(v0 - m) + expf(v1 - m) + expf(v2 - m) + expf(v3 - m);
            #pragma unroll
            for (int o = 8; o; o >>= 1) s += __shfl_xor_sync(0xffffffffu, s, o);
            float lse = m + logf(s);
            int gr = r0 + ty * 8 + i;
            if (gr < N) {
                *(float4*)&C[(size_t)gr * 64 + tx * 4] =
                    make_float4(v0 - lse, v1 - lse, v2 - lse, v3 - lse);
            }
        }
    }
}

// ---------------- launch ----------------
extern "C" void kernel_launch(void* const* d_in, const int* in_sizes, int n_in,
                              void* d_out, int out_size) {
    const float* x  = (const float*)d_in[0];
    const void*  ei = d_in[1];
    const float* W1 = (const float*)d_in[2];
    const float* b1 = (const float*)d_in[3];
    const float* W2 = (const float*)d_in[4];
    const float* b2 = (const float*)d_in[5];
    const float* W3 = (const float*)d_in[6];
    const float* b3 = (const float*)d_in[7];
    const float* W4 = (const float*)d_in[8];
    const float* b4 = (const float*)d_in[9];
    float* out = (float*)d_out;

    void *p_deg, *p_h1, *p_h2, *p_h3;
    cudaGetSymbolAddress(&p_deg, g_deg);
    cudaGetSymbolAddress(&p_h1, g_h1);
    cudaGetSymbolAddress(&p_h2, g_h2);
    cudaGetSymbolAddress(&p_h3, g_h3);
    float* h1 = (float*)p_h1;
    float* h2 = (float*)p_h2;
    float* h3 = (float*)p_h3;

    const int TB = 256;
    dim3 gg1((N_NODES + 127) / 128, 1);
    dim3 gg4((N_NODES + 127) / 128, 4);
    int agg_blocks = (N_NODES * 32 + TB - 1) / TB;

    // graph preprocessing
    k_detect<<<1, 32>>>((const int*)ei);
    cudaMemsetAsync(p_deg, 0, (size_t)N_NODES * sizeof(float));
    k_deg<<<(N_EDGES + TB - 1) / TB, TB>>>(ei);
    k_dinv<<<(N_NODES + TB - 1) / TB, TB>>>();
    k_scan1<<<SCAN_NB, 1024>>>();
    k_scan2<<<1, 128>>>();
    k_scan3<<<SCAN_NB, 1024>>>();
    k_fill<<<(N_EDGES + TB - 1) / TB, TB>>>(ei);

    // layer 1
    k_gemm<<<gg1, TB>>>(x, W1, nullptr, h1, N_NODES, IN_CH, HID1, 0, 0);
    k_agg<<<agg_blocks, TB>>>(h1, b1, h2);

    // layer 2
    k_gemm<<<gg1, TB>>>(h2, W2, nullptr, h1, N_NODES, HID1, HID2, 0, 0);
    k_agg<<<agg_blocks, TB>>>(h1, b2, h2);

    // layer 3
    k_gemm<<<gg4, TB>>>(h2, W3, b3, h3, N_NODES, HID2, HID3, 0, 0);

    // layer 4 + fused log_softmax
    k_gemm<<<gg1, TB>>>(h3, W4, b4, out, N_NODES, HID3, OUT_CH, 0, 1);
}

// round 6
// speedup vs baseline: 3.0776x; 1.4898x over previous
#include <cuda_runtime.h>
#include <cuda_bf16.h>

#define N_NODES 100000
#define N_EDGES 1600000
#define IN_CH 128
#define HID1 64
#define HID2 64
#define HID3 256
#define OUT_CH 64
#define SCAN_NB ((N_NODES + 1023) / 1024)   // 98

// ---------------- scratch (device globals; no allocation allowed) ----------------
__device__ float g_deg[N_NODES];
__device__ float g_dinv[N_NODES];
__device__ int   g_rs[N_NODES];                // CSR row start (exclusive scan)
__device__ int   g_cur[N_NODES];               // scatter cursors
__device__ int   g_bsum[128];                  // per-block scan sums
__device__ int   g_boff[128];                  // per-block offsets
__device__ int2  g_csr[N_EDGES];               // {src, norm-as-bits} grouped by dst
__device__ float g_h1[(size_t)N_NODES * 64];
__device__ float g_h2[(size_t)N_NODES * 64];
__device__ float g_W34[64 * 64];               // W3 @ W4 collapsed weight
__device__ float g_b34[64];                    // b3 @ W4 + b4
__device__ int   g_is64;

// ---------------- index dtype detection ----------------
__global__ void k_detect(const int* ei) {
    if (threadIdx.x == 0 && blockIdx.x == 0) {
        int is64 = 1;
        #pragma unroll 1
        for (int i = 0; i < 64; i++) {
            if (ei[2 * i + 1] != 0) { is64 = 0; break; }
        }
        g_is64 = is64;
    }
}

__device__ __forceinline__ int load_idx(const void* ei, long long i, int is64) {
    if (is64) return (int)__ldg(((const long long*)ei) + i);
    return __ldg(((const int*)ei) + i);
}

// ---------------- degree ----------------
__global__ void k_deg(const void* __restrict__ ei) {
    int e = blockIdx.x * blockDim.x + threadIdx.x;
    if (e >= N_EDGES) return;
    int d = load_idx(ei, (long long)N_EDGES + e, g_is64);
    atomicAdd(&g_deg[d], 1.0f);
}

__global__ void k_dinv() {
    int i = blockIdx.x * blockDim.x + threadIdx.x;
    if (i >= N_NODES) return;
    g_dinv[i] = rsqrtf(g_deg[i] + 1.0f);
}

// ---------------- collapse layers 3+4: W34 = W3@W4, b34 = b3@W4 + b4 ----------------
// grid 64 blocks (one per W34 row), 64 threads (one per col).
__global__ __launch_bounds__(64) void k_w34(const float* __restrict__ W3,
                                            const float* __restrict__ b3,
                                            const float* __restrict__ W4,
                                            const float* __restrict__ b4) {
    int i = blockIdx.x;
    int j = threadIdx.x;
    const float* w3r = W3 + (size_t)i * HID3;
    float acc = 0.0f;
    #pragma unroll 8
    for (int k = 0; k < HID3; k++) acc += w3r[k] * W4[(size_t)k * OUT_CH + j];
    g_W34[i * 64 + j] = acc;
    if (i == 0) {
        float bb = 0.0f;
        #pragma unroll 8
        for (int k = 0; k < HID3; k++) bb += b3[k] * W4[(size_t)k * OUT_CH + j];
        g_b34[j] = bb + b4[j];
    }
}

// ---------------- 3-phase multi-block exclusive scan ----------------
__global__ __launch_bounds__(1024) void k_scan1() {
    __shared__ int s[1024];
    int t = threadIdx.x;
    int i = blockIdx.x * 1024 + t;
    int v = (i < N_NODES) ? (int)g_deg[i] : 0;
    s[t] = v;
    __syncthreads();
    #pragma unroll 1
    for (int off = 1; off < 1024; off <<= 1) {
        int x = (t >= off) ? s[t - off] : 0;
        __syncthreads();
        s[t] += x;
        __syncthreads();
    }
    if (i < N_NODES) g_rs[i] = s[t] - v;   // exclusive within block
    if (t == 1023) g_bsum[blockIdx.x] = s[1023];
}

__global__ __launch_bounds__(128) void k_scan2() {
    __shared__ int s[128];
    int t = threadIdx.x;
    int v = (t < SCAN_NB) ? g_bsum[t] : 0;
    s[t] = v;
    __syncthreads();
    #pragma unroll 1
    for (int off = 1; off < 128; off <<= 1) {
        int x = (t >= off) ? s[t - off] : 0;
        __syncthreads();
        s[t] += x;
        __syncthreads();
    }
    if (t < SCAN_NB) g_boff[t] = s[t] - v;
}

__global__ __launch_bounds__(1024) void k_scan3() {
    int i = blockIdx.x * 1024 + threadIdx.x;
    if (i >= N_NODES) return;
    int r = g_rs[i] + g_boff[blockIdx.x];
    g_rs[i] = r;
    g_cur[i] = r;
}

// ---------------- fill CSR ----------------
__global__ void k_fill(const void* __restrict__ ei) {
    int e = blockIdx.x * blockDim.x + threadIdx.x;
    if (e >= N_EDGES) return;
    int is64 = g_is64;
    int s = load_idx(ei, e, is64);
    int d = load_idx(ei, (long long)N_EDGES + e, is64);
    float norm = g_dinv[s] * g_dinv[d];
    int pos = atomicAdd(&g_cur[d], 1);
    g_csr[pos] = make_int2(s, __float_as_int(norm));
}

// ---------------- fused aggregate + self-loop + bias + relu (64-wide) ----------------
__global__ __launch_bounds__(256) void k_agg(const float* __restrict__ h,
                                             const float* __restrict__ bias,
                                             float* __restrict__ out) {
    int warp = (int)((blockIdx.x * 256 + threadIdx.x) >> 5);
    int lane = threadIdx.x & 31;
    if (warp >= N_NODES) return;
    int i = warp;
    int start = g_rs[i];
    int end = start + (int)g_deg[i];
    float di = g_dinv[i];
    float sl = di * di;
    const float* hrow = h + ((size_t)i << 6);
    float acc0 = hrow[lane] * sl;
    float acc1 = hrow[lane + 32] * sl;
    int e = start;
    for (; e + 3 < end; e += 4) {
        int2 r0 = __ldg(&g_csr[e + 0]);
        int2 r1 = __ldg(&g_csr[e + 1]);
        int2 r2 = __ldg(&g_csr[e + 2]);
        int2 r3 = __ldg(&g_csr[e + 3]);
        const float* p0 = h + ((size_t)r0.x << 6);
        const float* p1 = h + ((size_t)r1.x << 6);
        const float* p2 = h + ((size_t)r2.x << 6);
        const float* p3 = h + ((size_t)r3.x << 6);
        float n0 = __int_as_float(r0.y), n1 = __int_as_float(r1.y);
        float n2 = __int_as_float(r2.y), n3 = __int_as_float(r3.y);
        float a00 = p0[lane], a01 = p0[lane + 32];
        float a10 = p1[lane], a11 = p1[lane + 32];
        float a20 = p2[lane], a21 = p2[lane + 32];
        float a30 = p3[lane], a31 = p3[lane + 32];
        acc0 += a00 * n0; acc1 += a01 * n0;
        acc0 += a10 * n1; acc1 += a11 * n1;
        acc0 += a20 * n2; acc1 += a21 * n2;
        acc0 += a30 * n3; acc1 += a31 * n3;
    }
    for (; e < end; e++) {
        int2 r = __ldg(&g_csr[e]);
        float n = __int_as_float(r.y);
        const float* p = h + ((size_t)r.x << 6);
        acc0 += p[lane] * n;
        acc1 += p[lane + 32] * n;
    }
    float v0 = acc0 + bias[lane];
    float v1 = acc1 + bias[lane + 32];
    out[((size_t)i << 6) + lane]      = fmaxf(v0, 0.0f);
    out[((size_t)i << 6) + lane + 32] = fmaxf(v1, 0.0f);
}

// ---------------- SGEMM: C[N,NOUT] = A[N,K] @ W[K,NOUT] (+bias) (+relu|lsm) ----------------
// BM=128, BN=64, BK=16, 256 threads, 8x4 microtile, double-buffered smem.
// lsm=1 requires NOUT==64 and gridDim.y==1 (full row in one block).
__global__ __launch_bounds__(256) void k_gemm(const float* __restrict__ A,
                                              const float* __restrict__ W,
                                              const float* __restrict__ bias,
                                              float* __restrict__ C,
                                              int N, int K, int NOUT,
                                              int relu, int lsm) {
    __shared__ float As[2][16][128];
    __shared__ float Bs[2][16][64];

    int r0 = blockIdx.x * 128;
    int c0 = blockIdx.y * 64;
    int tid = threadIdx.x;
    int tx = tid & 15;
    int ty = tid >> 4;

    int arow = tid >> 1;
    int ak8  = (tid & 1) << 3;
    int wrow = tid >> 4;
    int wc4  = (tid & 15) << 2;

    float acc[8][4];
    #pragma unroll
    for (int i = 0; i < 8; i++)
        #pragma unroll
        for (int j = 0; j < 4; j++) acc[i][j] = 0.0f;

    int nsteps = K >> 4;
    int gr_a = r0 + arow;

    // preload tile 0
    {
        float4 a0 = make_float4(0.f, 0.f, 0.f, 0.f);
        float4 a1 = make_float4(0.f, 0.f, 0.f, 0.f);
        if (gr_a < N) {
            const float* ap = A + (size_t)gr_a * K + ak8;
            a0 = *(const float4*)ap;
            a1 = *(const float4*)(ap + 4);
        }
        As[0][ak8 + 0][arow] = a0.x; As[0][ak8 + 1][arow] = a0.y;
        As[0][ak8 + 2][arow] = a0.z; As[0][ak8 + 3][arow] = a0.w;
        As[0][ak8 + 4][arow] = a1.x; As[0][ak8 + 5][arow] = a1.y;
        As[0][ak8 + 6][arow] = a1.z; As[0][ak8 + 7][arow] = a1.w;
        *(float4*)&Bs[0][wrow][wc4] = *(const float4*)&W[(size_t)wrow * NOUT + c0 + wc4];
    }
    __syncthreads();

    for (int t = 0; t < nsteps; t++) {
        int cur = t & 1;
        float4 a0, a1, wv;
        bool have_next = (t + 1 < nsteps);
        if (have_next) {
            int kk = (t + 1) << 4;
            a0 = make_float4(0.f, 0.f, 0.f, 0.f);
            a1 = make_float4(0.f, 0.f, 0.f, 0.f);
            if (gr_a < N) {
                const float* ap = A + (size_t)gr_a * K + kk + ak8;
                a0 = *(const float4*)ap;
                a1 = *(const float4*)(ap + 4);
            }
            wv = *(const float4*)&W[(size_t)(kk + wrow) * NOUT + c0 + wc4];
        }

        #pragma unroll
        for (int k = 0; k < 16; k++) {
            float4 b = *(const float4*)&Bs[cur][k][tx * 4];
            float ar[8];
            #pragma unroll
            for (int i = 0; i < 8; i++) ar[i] = As[cur][k][ty * 8 + i];
            #pragma unroll
            for (int i = 0; i < 8; i++) {
                acc[i][0] += ar[i] * b.x;
                acc[i][1] += ar[i] * b.y;
                acc[i][2] += ar[i] * b.z;
                acc[i][3] += ar[i] * b.w;
            }
        }

        if (have_next) {
            int nxt = cur ^ 1;
            As[nxt][ak8 + 0][arow] = a0.x; As[nxt][ak8 + 1][arow] = a0.y;
            As[nxt][ak8 + 2][arow] = a0.z; As[nxt][ak8 + 3][arow] = a0.w;
            As[nxt][ak8 + 4][arow] = a1.x; As[nxt][ak8 + 5][arow] = a1.y;
            As[nxt][ak8 + 6][arow] = a1.z; As[nxt][ak8 + 7][arow] = a1.w;
            *(float4*)&Bs[nxt][wrow][wc4] = wv;
            __syncthreads();
        }
    }

    float4 bv = make_float4(0.f, 0.f, 0.f, 0.f);
    if (bias) bv = *(const float4*)&bias[c0 + tx * 4];

    if (!lsm) {
        #pragma unroll
        for (int i = 0; i < 8; i++) {
            int gr = r0 + ty * 8 + i;
            if (gr < N) {
                float v0 = acc[i][0] + bv.x;
                float v1 = acc[i][1] + bv.y;
                float v2 = acc[i][2] + bv.z;
                float v3 = acc[i][3] + bv.w;
                if (relu) {
                    v0 = fmaxf(v0, 0.f); v1 = fmaxf(v1, 0.f);
                    v2 = fmaxf(v2, 0.f); v3 = fmaxf(v3, 0.f);
                }
                *(float4*)&C[(size_t)gr * NOUT + c0 + tx * 4] = make_float4(v0, v1, v2, v3);
            }
        }
    } else {
        // fused log_softmax over the 64 cols of each row (16 tx lanes x 4 cols,
        // within one half-warp; xor offsets 8/4/2/1 stay inside the row).
        #pragma unroll
        for (int i = 0; i < 8; i++) {
            float v0 = acc[i][0] + bv.x;
            float v1 = acc[i][1] + bv.y;
            float v2 = acc[i][2] + bv.z;
            float v3 = acc[i][3] + bv.w;
            float m = fmaxf(fmaxf(v0, v1), fmaxf(v2, v3));
            #pragma unroll
            for (int o = 8; o; o >>= 1) m = fmaxf(m, __shfl_xor_sync(0xffffffffu, m, o));
            float s = expf(v0 - m) + expf(v1 - m) + expf(v2 - m) + expf(v3 - m);
            #pragma unroll
            for (int o = 8; o; o >>= 1) s += __shfl_xor_sync(0xffffffffu, s, o);
            float lse = m + logf(s);
            int gr = r0 + ty * 8 + i;
            if (gr < N) {
                *(float4*)&C[(size_t)gr * 64 + tx * 4] =
                    make_float4(v0 - lse, v1 - lse, v2 - lse, v3 - lse);
            }
        }
    }
}

// ---------------- launch ----------------
extern "C" void kernel_launch(void* const* d_in, const int* in_sizes, int n_in,
                              void* d_out, int out_size) {
    const float* x  = (const float*)d_in[0];
    const void*  ei = d_in[1];
    const float* W1 = (const float*)d_in[2];
    const float* b1 = (const float*)d_in[3];
    const float* W2 = (const float*)d_in[4];
    const float* b2 = (const float*)d_in[5];
    const float* W3 = (const float*)d_in[6];
    const float* b3 = (const float*)d_in[7];
    const float* W4 = (const float*)d_in[8];
    const float* b4 = (const float*)d_in[9];
    float* out = (float*)d_out;

    void *p_deg, *p_h1, *p_h2, *p_w34, *p_b34;
    cudaGetSymbolAddress(&p_deg, g_deg);
    cudaGetSymbolAddress(&p_h1, g_h1);
    cudaGetSymbolAddress(&p_h2, g_h2);
    cudaGetSymbolAddress(&p_w34, g_W34);
    cudaGetSymbolAddress(&p_b34, g_b34);
    float* h1  = (float*)p_h1;
    float* h2  = (float*)p_h2;
    float* W34 = (float*)p_w34;
    float* b34 = (float*)p_b34;

    const int TB = 256;
    dim3 gg1((N_NODES + 127) / 128, 1);
    int agg_blocks = (N_NODES * 32 + TB - 1) / TB;

    // graph preprocessing + weight collapse (independent; same stream)
    k_detect<<<1, 32>>>((const int*)ei);
    cudaMemsetAsync(p_deg, 0, (size_t)N_NODES * sizeof(float));
    k_deg<<<(N_EDGES + TB - 1) / TB, TB>>>(ei);
    k_dinv<<<(N_NODES + TB - 1) / TB, TB>>>();
    k_scan1<<<SCAN_NB, 1024>>>();
    k_scan2<<<1, 128>>>();
    k_scan3<<<SCAN_NB, 1024>>>();
    k_fill<<<(N_EDGES + TB - 1) / TB, TB>>>(ei);
    k_w34<<<64, 64>>>(W3, b3, W4, b4);

    // layer 1
    k_gemm<<<gg1, TB>>>(x, W1, nullptr, h1, N_NODES, IN_CH, HID1, 0, 0);
    k_agg<<<agg_blocks, TB>>>(h1, b1, h2);

    // layer 2
    k_gemm<<<gg1, TB>>>(h2, W2, nullptr, h1, N_NODES, HID1, HID2, 0, 0);
    k_agg<<<agg_blocks, TB>>>(h1, b2, h2);

    // collapsed layers 3+4 + fused log_softmax
    k_gemm<<<gg1, TB>>>(h2, W34, b34, out, N_NODES, HID2, OUT_CH, 0, 1);
}

// round 9
// speedup vs baseline: 3.5628x; 1.1577x over previous
#include <cuda_runtime.h>
#include <cuda_bf16.h>

#define N_NODES 100000
#define N_EDGES 1600000
#define IN_CH 128
#define HID1 64
#define HID2 64
#define HID3 256
#define OUT_CH 64
#define SCAN_NB ((N_NODES + 1023) / 1024)   // 98

// ---------------- scratch (device globals; no allocation allowed) ----------------
__device__ float g_deg[N_NODES];
__device__ float g_dinv[N_NODES];
__device__ int   g_rs[N_NODES];                // CSR row start (exclusive scan)
__device__ int   g_cur[N_NODES];               // scatter cursors
__device__ int   g_bsum[128];                  // per-block scan sums
__device__ int   g_boff[128];                  // per-block offsets
__device__ int2  g_csr[N_EDGES];               // {src, norm-as-bits} grouped by dst
__device__ float g_h1[(size_t)N_NODES * 64];
__device__ float g_h2[(size_t)N_NODES * 64];
__device__ float g_W34[64 * 64];               // W3 @ W4 collapsed weight
__device__ float g_b34[64];                    // b3 @ W4 + b4
__device__ int   g_is64;                       // edge_index dtype flag

// ---------------- index dtype detection ----------------
__global__ void k_detect(const int* ei) {
    if (threadIdx.x == 0 && blockIdx.x == 0) {
        int is64 = 1;
        #pragma unroll 1
        for (int i = 0; i < 64; i++) {
            if (ei[2 * i + 1] != 0) { is64 = 0; break; }
        }
        g_is64 = is64;
    }
}

__device__ __forceinline__ int load_idx(const void* ei, long long i, int is64) {
    if (is64) return (int)__ldg(((const long long*)ei) + i);
    return __ldg(((const int*)ei) + i);
}

// ---------------- degree ----------------
__global__ void k_deg(const void* __restrict__ ei) {
    int e = blockIdx.x * blockDim.x + threadIdx.x;
    if (e >= N_EDGES) return;
    int d = load_idx(ei, (long long)N_EDGES + e, g_is64);
    atomicAdd(&g_deg[d], 1.0f);
}

// ---------------- collapse layers 3+4: W34 = W3@W4, b34 = b3@W4 + b4 ----------------
__global__ __launch_bounds__(64) void k_w34(const float* __restrict__ W3,
                                            const float* __restrict__ b3,
                                            const float* __restrict__ W4,
                                            const float* __restrict__ b4) {
    int i = blockIdx.x;
    int j = threadIdx.x;
    const float* w3r = W3 + (size_t)i * HID3;
    float acc = 0.0f;
    #pragma unroll 8
    for (int k = 0; k < HID3; k++) acc += w3r[k] * W4[(size_t)k * OUT_CH + j];
    g_W34[i * 64 + j] = acc;
    if (i == 0) {
        float bb = 0.0f;
        #pragma unroll 8
        for (int k = 0; k < HID3; k++) bb += b3[k] * W4[(size_t)k * OUT_CH + j];
        g_b34[j] = bb + b4[j];
    }
}

// ---------------- scan phase 1 (+ fused dinv) ----------------
__global__ __launch_bounds__(1024) void k_scan1() {
    __shared__ int s[1024];
    int t = threadIdx.x;
    int i = blockIdx.x * 1024 + t;
    float dg = (i < N_NODES) ? g_deg[i] : 0.0f;
    int v = (int)dg;
    if (i < N_NODES) g_dinv[i] = rsqrtf(dg + 1.0f);
    s[t] = v;
    __syncthreads();
    #pragma unroll 1
    for (int off = 1; off < 1024; off <<= 1) {
        int x = (t >= off) ? s[t - off] : 0;
        __syncthreads();
        s[t] += x;
        __syncthreads();
    }
    if (i < N_NODES) g_rs[i] = s[t] - v;   // exclusive within block
    if (t == 1023) g_bsum[blockIdx.x] = s[1023];
}

__global__ __launch_bounds__(128) void k_scan2() {
    __shared__ int s[128];
    int t = threadIdx.x;
    int v = (t < SCAN_NB) ? g_bsum[t] : 0;
    s[t] = v;
    __syncthreads();
    #pragma unroll 1
    for (int off = 1; off < 128; off <<= 1) {
        int x = (t >= off) ? s[t - off] : 0;
        __syncthreads();
        s[t] += x;
        __syncthreads();
    }
    if (t < SCAN_NB) g_boff[t] = s[t] - v;
}

__global__ __launch_bounds__(1024) void k_scan3() {
    int i = blockIdx.x * 1024 + threadIdx.x;
    if (i >= N_NODES) return;
    int r = g_rs[i] + g_boff[blockIdx.x];
    g_rs[i] = r;
    g_cur[i] = r;
}

// ---------------- fill CSR ----------------
__global__ void k_fill(const void* __restrict__ ei) {
    int e = blockIdx.x * blockDim.x + threadIdx.x;
    if (e >= N_EDGES) return;
    int is64 = g_is64;
    int s = load_idx(ei, e, is64);
    int d = load_idx(ei, (long long)N_EDGES + e, is64);
    float norm = g_dinv[s] * g_dinv[d];
    int pos = atomicAdd(&g_cur[d], 1);
    g_csr[pos] = make_int2(s, __float_as_int(norm));
}

// ---------------- fused aggregate + self-loop + bias + relu (64-wide) ----------------
__global__ __launch_bounds__(256) void k_agg(const float* __restrict__ h,
                                             const float* __restrict__ bias,
                                             float* __restrict__ out) {
    int warp = (int)((blockIdx.x * 256 + threadIdx.x) >> 5);
    int lane = threadIdx.x & 31;
    if (warp >= N_NODES) return;
    int i = warp;
    int start = g_rs[i];
    int end = start + (int)g_deg[i];
    float di = g_dinv[i];
    float sl = di * di;
    const float* hrow = h + ((size_t)i << 6);
    float acc0 = hrow[lane] * sl;
    float acc1 = hrow[lane + 32] * sl;
    int e = start;
    for (; e + 3 < end; e += 4) {
        int2 r0 = __ldg(&g_csr[e + 0]);
        int2 r1 = __ldg(&g_csr[e + 1]);
        int2 r2 = __ldg(&g_csr[e + 2]);
        int2 r3 = __ldg(&g_csr[e + 3]);
        const float* p0 = h + ((size_t)r0.x << 6);
        const float* p1 = h + ((size_t)r1.x << 6);
        const float* p2 = h + ((size_t)r2.x << 6);
        const float* p3 = h + ((size_t)r3.x << 6);
        float n0 = __int_as_float(r0.y), n1 = __int_as_float(r1.y);
        float n2 = __int_as_float(r2.y), n3 = __int_as_float(r3.y);
        float a00 = p0[lane], a01 = p0[lane + 32];
        float a10 = p1[lane], a11 = p1[lane + 32];
        float a20 = p2[lane], a21 = p2[lane + 32];
        float a30 = p3[lane], a31 = p3[lane + 32];
        acc0 += a00 * n0; acc1 += a01 * n0;
        acc0 += a10 * n1; acc1 += a11 * n1;
        acc0 += a20 * n2; acc1 += a21 * n2;
        acc0 += a30 * n3; acc1 += a31 * n3;
    }
    for (; e < end; e++) {
        int2 r = __ldg(&g_csr[e]);
        float n = __int_as_float(r.y);
        const float* p = h + ((size_t)r.x << 6);
        acc0 += p[lane] * n;
        acc1 += p[lane + 32] * n;
    }
    float v0 = acc0 + bias[lane];
    float v1 = acc1 + bias[lane + 32];
    out[((size_t)i << 6) + lane]      = fmaxf(v0, 0.0f);
    out[((size_t)i << 6) + lane + 32] = fmaxf(v1, 0.0f);
}

// ---------------- SGEMM: C[N,NOUT] = A[N,K] @ W[K,NOUT] (+bias) (+relu|lsm) ----------------
// BM=128, BN=64, BK=16, 256 threads, 8x4 microtile, double-buffered smem.
// lsm=1 requires NOUT==64 and gridDim.y==1 (full row in one block).
__global__ __launch_bounds__(256) void k_gemm(const float* __restrict__ A,
                                              const float* __restrict__ W,
                                              const float* __restrict__ bias,
                                              float* __restrict__ C,
                                              int N, int K, int NOUT,
                                              int relu, int lsm) {
    __shared__ float As[2][16][128];
    __shared__ float Bs[2][16][64];

    int r0 = blockIdx.x * 128;
    int c0 = blockIdx.y * 64;
    int tid = threadIdx.x;
    int tx = tid & 15;
    int ty = tid >> 4;

    int arow = tid >> 1;
    int ak8  = (tid & 1) << 3;
    int wrow = tid >> 4;
    int wc4  = (tid & 15) << 2;

    float acc[8][4];
    #pragma unroll
    for (int i = 0; i < 8; i++)
        #pragma unroll
        for (int j = 0; j < 4; j++) acc[i][j] = 0.0f;

    int nsteps = K >> 4;
    int gr_a = r0 + arow;

    // preload tile 0
    {
        float4 a0 = make_float4(0.f, 0.f, 0.f, 0.f);
        float4 a1 = make_float4(0.f, 0.f, 0.f, 0.f);
        if (gr_a < N) {
            const float* ap = A + (size_t)gr_a * K + ak8;
            a0 = *(const float4*)ap;
            a1 = *(const float4*)(ap + 4);
        }
        As[0][ak8 + 0][arow] = a0.x; As[0][ak8 + 1][arow] = a0.y;
        As[0][ak8 + 2][arow] = a0.z; As[0][ak8 + 3][arow] = a0.w;
        As[0][ak8 + 4][arow] = a1.x; As[0][ak8 + 5][arow] = a1.y;
        As[0][ak8 + 6][arow] = a1.z; As[0][ak8 + 7][arow] = a1.w;
        *(float4*)&Bs[0][wrow][wc4] = *(const float4*)&W[(size_t)wrow * NOUT + c0 + wc4];
    }
    __syncthreads();

    for (int t = 0; t < nsteps; t++) {
        int cur = t & 1;
        float4 a0, a1, wv;
        bool have_next = (t + 1 < nsteps);
        if (have_next) {
            int kk = (t + 1) << 4;
            a0 = make_float4(0.f, 0.f, 0.f, 0.f);
            a1 = make_float4(0.f, 0.f, 0.f, 0.f);
            if (gr_a < N) {
                const float* ap = A + (size_t)gr_a * K + kk + ak8;
                a0 = *(const float4*)ap;
                a1 = *(const float4*)(ap + 4);
            }
            wv = *(const float4*)&W[(size_t)(kk + wrow) * NOUT + c0 + wc4];
        }

        #pragma unroll
        for (int k = 0; k < 16; k++) {
            float4 b = *(const float4*)&Bs[cur][k][tx * 4];
            float ar[8];
            #pragma unroll
            for (int i = 0; i < 8; i++) ar[i] = As[cur][k][ty * 8 + i];
            #pragma unroll
            for (int i = 0; i < 8; i++) {
                acc[i][0] += ar[i] * b.x;
                acc[i][1] += ar[i] * b.y;
                acc[i][2] += ar[i] * b.z;
                acc[i][3] += ar[i] * b.w;
            }
        }

        if (have_next) {
            int nxt = cur ^ 1;
            As[nxt][ak8 + 0][arow] = a0.x; As[nxt][ak8 + 1][arow] = a0.y;
            As[nxt][ak8 + 2][arow] = a0.z; As[nxt][ak8 + 3][arow] = a0.w;
            As[nxt][ak8 + 4][arow] = a1.x; As[nxt][ak8 + 5][arow] = a1.y;
            As[nxt][ak8 + 6][arow] = a1.z; As[nxt][ak8 + 7][arow] = a1.w;
            *(float4*)&Bs[nxt][wrow][wc4] = wv;
            __syncthreads();
        }
    }

    float4 bv = make_float4(0.f, 0.f, 0.f, 0.f);
    if (bias) bv = *(const float4*)&bias[c0 + tx * 4];

    if (!lsm) {
        #pragma unroll
        for (int i = 0; i < 8; i++) {
            int gr = r0 + ty * 8 + i;
            if (gr < N) {
                float v0 = acc[i][0] + bv.x;
                float v1 = acc[i][1] + bv.y;
                float v2 = acc[i][2] + bv.z;
                float v3 = acc[i][3] + bv.w;
                if (relu) {
                    v0 = fmaxf(v0, 0.f); v1 = fmaxf(v1, 0.f);
                    v2 = fmaxf(v2, 0.f); v3 = fmaxf(v3, 0.f);
                }
                *(float4*)&C[(size_t)gr * NOUT + c0 + tx * 4] = make_float4(v0, v1, v2, v3);
            }
        }
    } else {
        // fused log_softmax over the 64 cols of each row (16 tx lanes x 4 cols,
        // within one half-warp; xor offsets 8/4/2/1 stay inside the row).
        #pragma unroll
        for (int i = 0; i < 8; i++) {
            float v0 = acc[i][0] + bv.x;
            float v1 = acc[i][1] + bv.y;
            float v2 = acc[i][2] + bv.z;
            float v3 = acc[i][3] + bv.w;
            float m = fmaxf(fmaxf(v0, v1), fmaxf(v2, v3));
            #pragma unroll
            for (int o = 8; o; o >>= 1) m = fmaxf(m, __shfl_xor_sync(0xffffffffu, m, o));
            float s = expf(v0 - m) + expf(v1 - m) + expf(v2 - m) + expf(v3 - m);
            #pragma unroll
            for (int o = 8; o; o >>= 1) s += __shfl_xor_sync(0xffffffffu, s, o);
            float lse = m + logf(s);
            int gr = r0 + ty * 8 + i;
            if (gr < N) {
                *(float4*)&C[(size_t)gr * 64 + tx * 4] =
                    make_float4(v0 - lse, v1 - lse, v2 - lse, v3 - lse);
            }
        }
    }
}

// ---------------- launch ----------------
extern "C" void kernel_launch(void* const* d_in, const int* in_sizes, int n_in,
                              void* d_out, int out_size) {
    const float* x  = (const float*)d_in[0];
    const void*  ei = d_in[1];
    const float* W1 = (const float*)d_in[2];
    const float* b1 = (const float*)d_in[3];
    const float* W2 = (const float*)d_in[4];
    const float* b2 = (const float*)d_in[5];
    const float* W3 = (const float*)d_in[6];
    const float* b3 = (const float*)d_in[7];
    const float* W4 = (const float*)d_in[8];
    const float* b4 = (const float*)d_in[9];
    float* out = (float*)d_out;

    void *p_deg, *p_h1, *p_h2, *p_w34, *p_b34;
    cudaGetSymbolAddress(&p_deg, g_deg);
    cudaGetSymbolAddress(&p_h1, g_h1);
    cudaGetSymbolAddress(&p_h2, g_h2);
    cudaGetSymbolAddress(&p_w34, g_W34);
    cudaGetSymbolAddress(&p_b34, g_b34);
    float* h1  = (float*)p_h1;
    float* h2  = (float*)p_h2;
    float* W34 = (float*)p_w34;
    float* b34 = (float*)p_b34;

    // Side stream + events for fork-join. Created once during the (non-captured)
    // correctness call; replay cost zero. If ANY creation fails, fall back to
    // fully serial single-stream ordering (known-good R6 path).
    static cudaStream_t s2 = nullptr;
    static cudaEvent_t ev_fork = nullptr, ev_join = nullptr;
    static int use_fork = -1;
    if (use_fork < 0) {
        use_fork = 1;
        if (cudaStreamCreateWithFlags(&s2, cudaStreamNonBlocking) != cudaSuccess) use_fork = 0;
        if (use_fork && cudaEventCreateWithFlags(&ev_fork, cudaEventDisableTiming) != cudaSuccess) use_fork = 0;
        if (use_fork && cudaEventCreateWithFlags(&ev_join, cudaEventDisableTiming) != cudaSuccess) use_fork = 0;
        if (!use_fork) s2 = nullptr;
        cudaGetLastError();  // clear any error state
    }
    cudaStream_t sp = use_fork ? s2 : (cudaStream_t)0;  // prep-chain stream

    const int TB = 256;
    dim3 gg1((N_NODES + 127) / 128, 1);
    int agg_blocks = (N_NODES * 32 + TB - 1) / TB;

    // ---- fork: CSR/prep chain on sp (touches only edge_index + prep scratch)
    if (use_fork) {
        cudaEventRecord(ev_fork, 0);
        cudaStreamWaitEvent(sp, ev_fork, 0);
    }
    k_detect<<<1, 32, 0, sp>>>((const int*)ei);
    cudaMemsetAsync(p_deg, 0, (size_t)N_NODES * sizeof(float), sp);
    k_deg<<<(N_EDGES + TB - 1) / TB, TB, 0, sp>>>(ei);
    k_scan1<<<SCAN_NB, 1024, 0, sp>>>();   // also writes g_dinv
    k_scan2<<<1, 128, 0, sp>>>();
    k_scan3<<<SCAN_NB, 1024, 0, sp>>>();
    k_fill<<<(N_EDGES + TB - 1) / TB, TB, 0, sp>>>(ei);
    if (use_fork) cudaEventRecord(ev_join, sp);

    // ---- main stream meanwhile: layer-1 GEMM + weight collapse (disjoint data)
    k_gemm<<<gg1, TB>>>(x, W1, nullptr, h1, N_NODES, IN_CH, HID1, 0, 0);
    k_w34<<<64, 64>>>(W3, b3, W4, b4);

    // ---- join
    if (use_fork) cudaStreamWaitEvent((cudaStream_t)0, ev_join, 0);

    // layer 1 aggregate
    k_agg<<<agg_blocks, TB>>>(h1, b1, h2);

    // layer 2
    k_gemm<<<gg1, TB>>>(h2, W2, nullptr, h1, N_NODES, HID1, HID2, 0, 0);
    k_agg<<<agg_blocks, TB>>>(h1, b2, h2);

    // collapsed layers 3+4 + fused log_softmax
    k_gemm<<<gg1, TB>>>(h2, W34, b34, out, N_NODES, HID2, OUT_CH, 0, 1);
}